// round 1
// baseline (speedup 1.0000x reference)
#include <cuda_runtime.h>

#define NN 32
#define CC 64
#define TT 512
#define VV 25
#define HH 3
#define TS 4
#define NT (NN*TT)              // 16384 slices
#define TOTAL (NN*CC*TT*VV)     // 26214400
#define UP 28                   // u padded to 28 (16B-aligned rows)
#define CNT_F (NN*TT*VV)        // 409600 elements per channel

typedef unsigned long long ull;

// scratch (no cudaMalloc allowed)
__device__ float g_conv[TOTAL];     // pre-BN conv output
__device__ float g_Wt[HH*CC*CC];    // W transposed to [h][c][o]
__device__ float g_stats[128];      // [0:64) sum, [64:128) sumsq
__device__ float g_scale[CC];
__device__ float g_shift[CC];

__device__ __forceinline__ ull fma2(ull a, ull b, ull c) {
    ull d;
    asm("fma.rn.f32x2 %0, %1, %2, %3;" : "=l"(d) : "l"(a), "l"(b), "l"(c));
    return d;
}
__device__ __forceinline__ ull pack2(float v) {
    ull r;
    asm("mov.b64 %0, {%1, %1};" : "=l"(r) : "f"(v));
    return r;
}
__device__ __forceinline__ float2 unpack2(ull v) {
    float2 r;
    asm("mov.b64 {%0, %1}, %2;" : "=f"(r.x), "=f"(r.y) : "l"(v));
    return r;
}

// ---------------------------------------------------------------------------
// prep: transpose W [h][o][c] -> g_Wt [h][c][o], zero the stats accumulators
// ---------------------------------------------------------------------------
__global__ void prep_k(const float* __restrict__ W) {
    int i = blockIdx.x * blockDim.x + threadIdx.x;
    if (i < HH*CC*CC) {
        int h = i >> 12;
        int rem = i & 4095;
        int o = rem >> 6;
        int c = rem & 63;
        g_Wt[(h << 12) + (c << 6) + o] = W[i];
    }
    if (i < 128) g_stats[i] = 0.f;
}

// ---------------------------------------------------------------------------
// pass 1: per-slice conv (graph conv + channel mix over heads), stats
// 1 warp = 1 (n,t) slice; lane owns channels o0=2*lane, o1=2*lane+1
// ---------------------------------------------------------------------------
__global__ __launch_bounds__(128) void conv_pass(const float* __restrict__ x,
                                                 const float* __restrict__ A) {
    __shared__ __align__(16) float smA[HH*VV*UP];   // 2100 floats
    __shared__ float smStat[128];
    __shared__ __align__(16) float smX[TS*CC*UP];   // 7168 floats (also reused as Sout[64][104])

    const int tid  = threadIdx.x;
    const int sub  = tid >> 5;          // slice within CTA (= warp id)
    const int lane = tid & 31;
    const int slice0 = blockIdx.x * TS;
    const int n  = slice0 >> 9;         // /512
    const int t0 = slice0 & (TT - 1);

    // --- load A into smem with zero padding u in [25,28) ---
    for (int i = tid; i < HH*VV*VV; i += 128) {
        int h = i / (VV*VV);
        int rem = i - h*VV*VV;
        int v = rem / VV;
        int u = rem - v*VV;
        smA[(h*VV + v)*UP + u] = A[i];
    }
    for (int i = tid; i < HH*VV*3; i += 128) {
        int h = i / (VV*3);
        int rem = i - h*VV*3;
        int v = rem / 3;
        int u = VV + (rem - v*3);
        smA[(h*VV + v)*UP + u] = 0.f;
    }
    smStat[tid] = 0.f;   // blockDim == 128, covers all

    // --- X tile pads ---
    for (int i = tid; i < TS*CC*3; i += 128) {
        int s = i / (CC*3);
        int rem = i - s*CC*3;
        int c = rem / 3;
        int u = VV + (rem - c*3);
        smX[(s*CC + c)*UP + u] = 0.f;
    }
    // --- cooperative X load: 100 contiguous floats (4 t's) per channel c ---
    const float4* x4 = reinterpret_cast<const float4*>(x);
    for (int idx = tid; idx < CC*VV; idx += 128) {
        int c = idx / VV;
        int q = idx - c*VV;                       // float4 index within the 100-float run
        unsigned gb = ((unsigned)(n*CC + c)*TT + t0)*VV;   // divisible by 100
        float4 val = x4[(gb >> 2) + q];
        float vv[4] = {val.x, val.y, val.z, val.w};
        int r0 = q * 4;
        #pragma unroll
        for (int e = 0; e < 4; ++e) {
            int r = r0 + e;
            int s = r / VV;
            int u = r - s*VV;
            smX[(s*CC + c)*UP + u] = vv[e];
        }
    }
    __syncthreads();

    // --- compute ---
    ull oP0[VV], oP1[VV];
    #pragma unroll
    for (int v = 0; v < VV; ++v) { oP0[v] = 0ull; oP1[v] = 0ull; }

    const ulonglong2* xbase = reinterpret_cast<const ulonglong2*>(smX + sub*CC*UP);

    for (int h = 0; h < HH; ++h) {
        // GEMM1: y[o][u] = sum_c W[h][o][c] * X[c][u]
        ull y0[14], y1[14];
        #pragma unroll
        for (int j = 0; j < 14; ++j) { y0[j] = 0ull; y1[j] = 0ull; }

        const float2* wt = reinterpret_cast<const float2*>(g_Wt + h*CC*CC) + lane;
        for (int c = 0; c < CC; ++c) {
            float2 wp = __ldg(wt + c*32);         // (W[h][o0][c], W[h][o1][c])
            ull w0 = pack2(wp.x);
            ull w1 = pack2(wp.y);
            const ulonglong2* xr = xbase + c*7;
            #pragma unroll
            for (int jj = 0; jj < 7; ++jj) {
                ulonglong2 xq = xr[jj];
                y0[2*jj]   = fma2(w0, xq.x, y0[2*jj]);
                y1[2*jj]   = fma2(w1, xq.x, y1[2*jj]);
                y0[2*jj+1] = fma2(w0, xq.y, y0[2*jj+1]);
                y1[2*jj+1] = fma2(w1, xq.y, y1[2*jj+1]);
            }
        }
        // GEMM2: out[o][v] += sum_u y[o][u] * A[h][v][u]
        const ulonglong2* abase = reinterpret_cast<const ulonglong2*>(smA + h*VV*UP);
        #pragma unroll
        for (int v = 0; v < VV; ++v) {
            const ulonglong2* ar = abase + v*7;
            #pragma unroll
            for (int jj = 0; jj < 7; ++jj) {
                ulonglong2 aq = ar[jj];
                oP0[v] = fma2(y0[2*jj],   aq.x, oP0[v]);
                oP1[v] = fma2(y1[2*jj],   aq.x, oP1[v]);
                oP0[v] = fma2(y0[2*jj+1], aq.y, oP0[v]);
                oP1[v] = fma2(y1[2*jj+1], aq.y, oP1[v]);
            }
        }
    }

    // --- epilogue: stage results + per-channel stats ---
    const int o0 = 2*lane, o1 = o0 + 1;
    __syncthreads();                    // everyone done reading smX
    float* Sout = smX;                  // reuse as [64][104]
    float s10 = 0.f, s20 = 0.f, s11 = 0.f, s21 = 0.f;
    #pragma unroll
    for (int v = 0; v < VV; ++v) {
        float2 p0 = unpack2(oP0[v]);
        float a = p0.x + p0.y;
        float2 p1 = unpack2(oP1[v]);
        float b = p1.x + p1.y;
        Sout[o0*104 + sub*VV + v] = a;
        Sout[o1*104 + sub*VV + v] = b;
        s10 += a; s20 += a*a;
        s11 += b; s21 += b*b;
    }
    atomicAdd(&smStat[o0],      s10);
    atomicAdd(&smStat[64 + o0], s20);
    atomicAdd(&smStat[o1],      s11);
    atomicAdd(&smStat[64 + o1], s21);
    __syncthreads();
    atomicAdd(&g_stats[tid], smStat[tid]);

    // --- coalesced float4 store of the conv output ---
    float4* cv4 = reinterpret_cast<float4*>(g_conv);
    for (int idx = tid; idx < CC*VV; idx += 128) {
        int o = idx / VV;
        int q = idx - o*VV;
        float4 val = *reinterpret_cast<const float4*>(Sout + o*104 + q*4);
        unsigned gb = ((unsigned)(n*CC + o)*TT + t0)*VV;
        cv4[(gb >> 2) + q] = val;
    }
}

// ---------------------------------------------------------------------------
// stats: fold mean/var into per-channel scale/shift
// ---------------------------------------------------------------------------
__global__ void stats_k(const float* __restrict__ gamma, const float* __restrict__ beta) {
    int o = threadIdx.x;
    if (o < CC) {
        const float inv = 1.f / (float)CNT_F;
        float mean = g_stats[o] * inv;
        float var  = g_stats[64 + o] * inv - mean*mean;
        float sc = gamma[o] * rsqrtf(var + 1e-5f);
        g_scale[o] = sc;
        g_shift[o] = beta[o] - mean*sc;
    }
}

// ---------------------------------------------------------------------------
// pass 2: out = relu(scale[c]*conv + shift[c] + x), streaming float4
// ---------------------------------------------------------------------------
__global__ void bn_apply(const float4* __restrict__ xv, float4* __restrict__ ov) {
    const float4* cv = reinterpret_cast<const float4*>(g_conv);
    const int n4 = TOTAL / 4;
    int stride = gridDim.x * blockDim.x;
    for (int i = blockIdx.x * blockDim.x + threadIdx.x; i < n4; i += stride) {
        int c = (i / 3200) & 63;        // 3200 float4 per (n,c) chunk
        float s  = __ldg(&g_scale[c]);
        float sh = __ldg(&g_shift[c]);
        float4 a = cv[i];
        float4 b = xv[i];
        float4 r;
        r.x = fmaxf(fmaf(s, a.x, sh) + b.x, 0.f);
        r.y = fmaxf(fmaf(s, a.y, sh) + b.y, 0.f);
        r.z = fmaxf(fmaf(s, a.z, sh) + b.z, 0.f);
        r.w = fmaxf(fmaf(s, a.w, sh) + b.w, 0.f);
        ov[i] = r;
    }
}

// ---------------------------------------------------------------------------
extern "C" void kernel_launch(void* const* d_in, const int* in_sizes, int n_in,
                              void* d_out, int out_size) {
    const float* x     = (const float*)d_in[0];
    const float* A     = (const float*)d_in[1];
    const float* W     = (const float*)d_in[2];
    // d_in[3] = b : cancels exactly under training-mode BatchNorm -> unused
    const float* gamma = (const float*)d_in[4];
    const float* beta  = (const float*)d_in[5];
    float* out = (float*)d_out;

    prep_k<<<48, 256>>>(W);
    conv_pass<<<NT/TS, 128>>>(x, A);
    stats_k<<<1, 64>>>(gamma, beta);
    bn_apply<<<4096, 256>>>(reinterpret_cast<const float4*>(x),
                            reinterpret_cast<float4*>(out));
}

// round 3
// speedup vs baseline: 1.0596x; 1.0596x over previous
#include <cuda_runtime.h>

#define NN 32
#define CC 64
#define TT 512
#define VV 25
#define HH 3
#define TS 4
#define NT (NN*TT)              // 16384 slices
#define TOTAL (NN*CC*TT*VV)     // 26214400
#define UP 28                   // u padded to 28 (16B-aligned rows)
#define CNT_F (NN*TT*VV)        // 409600 elements per channel

typedef unsigned long long ull;

// scratch (no cudaMalloc allowed)
__device__ float g_conv[TOTAL];     // pre-BN conv output
__device__ float g_Wt[HH*CC*CC];    // W transposed to [h][c][o]
__device__ float g_stats[128];      // [0:64) sum, [64:128) sumsq
__device__ float g_scale[CC];
__device__ float g_shift[CC];

__device__ __forceinline__ ull fma2(ull a, ull b, ull c) {
    ull d;
    asm("fma.rn.f32x2 %0, %1, %2, %3;" : "=l"(d) : "l"(a), "l"(b), "l"(c));
    return d;
}
__device__ __forceinline__ ull pack2(float v) {
    ull r;
    asm("mov.b64 %0, {%1, %1};" : "=l"(r) : "f"(v));
    return r;
}
__device__ __forceinline__ float2 unpack2(ull v) {
    float2 r;
    asm("mov.b64 {%0, %1}, %2;" : "=f"(r.x), "=f"(r.y) : "l"(v));
    return r;
}

// ---------------------------------------------------------------------------
// prep: transpose W [h][o][c] -> g_Wt [h][c][o], zero the stats accumulators
// ---------------------------------------------------------------------------
__global__ void prep_k(const float* __restrict__ W) {
    int i = blockIdx.x * blockDim.x + threadIdx.x;
    if (i < HH*CC*CC) {
        int h = i >> 12;
        int rem = i & 4095;
        int o = rem >> 6;
        int c = rem & 63;
        g_Wt[(h << 12) + (c << 6) + o] = W[i];
    }
    if (i < 128) g_stats[i] = 0.f;
}

// ---------------------------------------------------------------------------
// pass 1: per-slice conv (graph conv + channel mix over heads), stats
// 1 warp = 1 (n,t) slice; lane owns channels o0=2*lane, o1=2*lane+1
// Output accumulators packed over v-PAIRS (p=0..12; p12.y is pad v=25)
// ---------------------------------------------------------------------------
__global__ __launch_bounds__(128, 3) void conv_pass(const float* __restrict__ x,
                                                    const float* __restrict__ A) {
    __shared__ __align__(16) float smAt[HH*UP*UP];  // A transposed: [h][u][v], 2352 floats
    __shared__ float smStat[128];
    __shared__ __align__(16) float smX[TS*CC*UP];   // 7168 floats (reused as Sout[64][104])

    const int tid  = threadIdx.x;
    const int sub  = tid >> 5;          // slice within CTA (= warp id)
    const int lane = tid & 31;
    const int slice0 = blockIdx.x * TS;
    const int n  = slice0 >> 9;         // /512
    const int t0 = slice0 & (TT - 1);

    // --- load A TRANSPOSED into smem: smAt[(h*UP + u)*UP + v] = A[h][v][u] ---
    for (int i = tid; i < HH*UP*UP; i += 128) {
        int h = i / (UP*UP);
        int rem = i - h*UP*UP;
        int u = rem / UP;
        int v = rem - u*UP;
        float val = 0.f;
        if (u < VV && v < VV) val = A[(h*VV + v)*VV + u];
        smAt[i] = val;
    }
    smStat[tid] = 0.f;

    // --- X tile pads (u in [25,28)) ---
    for (int i = tid; i < TS*CC*3; i += 128) {
        int s = i / (CC*3);
        int rem = i - s*CC*3;
        int c = rem / 3;
        int u = VV + (rem - c*3);
        smX[(s*CC + c)*UP + u] = 0.f;
    }
    // --- cooperative X load: 100 contiguous floats (4 t's) per channel c ---
    const float4* x4 = reinterpret_cast<const float4*>(x);
    for (int idx = tid; idx < CC*VV; idx += 128) {
        int c = idx / VV;
        int q = idx - c*VV;                       // float4 index within the 100-float run
        unsigned gb = ((unsigned)(n*CC + c)*TT + t0)*VV;   // divisible by 100
        float4 val = x4[(gb >> 2) + q];
        float vv[4] = {val.x, val.y, val.z, val.w};
        int r0 = q * 4;
        #pragma unroll
        for (int e = 0; e < 4; ++e) {
            int r = r0 + e;
            int s = r / VV;
            int u = r - s*VV;
            smX[(s*CC + c)*UP + u] = vv[e];
        }
    }
    __syncthreads();

    // --- compute ---
    ull oP0[13], oP1[13];
    #pragma unroll
    for (int p = 0; p < 13; ++p) { oP0[p] = 0ull; oP1[p] = 0ull; }

    const ulonglong2* xbase = reinterpret_cast<const ulonglong2*>(smX + sub*CC*UP);

    for (int h = 0; h < HH; ++h) {
        // GEMM1: y[o][u] = sum_c W[h][o][c] * X[c][u]  (u-pair packed)
        ull y0[14], y1[14];
        #pragma unroll
        for (int j = 0; j < 14; ++j) { y0[j] = 0ull; y1[j] = 0ull; }

        const float2* wt = reinterpret_cast<const float2*>(g_Wt + h*CC*CC) + lane;
        #pragma unroll 4
        for (int c = 0; c < CC; ++c) {
            float2 wp = __ldg(wt + c*32);         // (W[h][o0][c], W[h][o1][c])
            ull w0 = pack2(wp.x);
            ull w1 = pack2(wp.y);
            const ulonglong2* xr = xbase + c*7;
            #pragma unroll
            for (int jj = 0; jj < 7; ++jj) {
                ulonglong2 xq = xr[jj];
                y0[2*jj]   = fma2(w0, xq.x, y0[2*jj]);
                y1[2*jj]   = fma2(w1, xq.x, y1[2*jj]);
                y0[2*jj+1] = fma2(w0, xq.y, y0[2*jj+1]);
                y1[2*jj+1] = fma2(w1, xq.y, y1[2*jj+1]);
            }
        }

        // GEMM2: oP[o][vp] += y[o][u] * At[u][vp]  (v-pair packed, A rows = u)
        const float* abase = smAt + h*UP*UP;
        #pragma unroll 2
        for (int j = 0; j < 14; ++j) {
            // unpack u-pair (2j, 2j+1) for both channels, dup-pack each scalar
            float2 ya = unpack2(y0[j]);
            float2 yb = unpack2(y1[j]);
            ull d0a = pack2(ya.x), d0b = pack2(ya.y);
            ull d1a = pack2(yb.x), d1b = pack2(yb.y);
            #pragma unroll
            for (int r = 0; r < 2; ++r) {
                int u = 2*j + r;
                ull du0 = r ? d0b : d0a;
                ull du1 = r ? d1b : d1a;
                const ulonglong2* ar = reinterpret_cast<const ulonglong2*>(abase + u*UP);
                #pragma unroll
                for (int qq = 0; qq < 6; ++qq) {
                    ulonglong2 aq = ar[qq];                 // v-pairs 2qq, 2qq+1
                    oP0[2*qq]   = fma2(du0, aq.x, oP0[2*qq]);
                    oP1[2*qq]   = fma2(du1, aq.x, oP1[2*qq]);
                    oP0[2*qq+1] = fma2(du0, aq.y, oP0[2*qq+1]);
                    oP1[2*qq+1] = fma2(du1, aq.y, oP1[2*qq+1]);
                }
                // p = 12 (v=24,25): ull index 12 = floats 24,25 of the row
                ull a12 = reinterpret_cast<const ull*>(abase + u*UP)[12];
                oP0[12] = fma2(du0, a12, oP0[12]);
                oP1[12] = fma2(du1, a12, oP1[12]);
            }
        }
    }

    // --- epilogue: stage results + per-channel stats ---
    const int o0 = 2*lane, o1 = o0 + 1;
    __syncthreads();                    // everyone done reading smX
    float* Sout = smX;                  // reuse as [64][104]
    float s10 = 0.f, s20 = 0.f, s11 = 0.f, s21 = 0.f;
    #pragma unroll
    for (int p = 0; p < 13; ++p) {
        float2 a = unpack2(oP0[p]);
        float2 b = unpack2(oP1[p]);
        int v = 2*p;
        Sout[o0*104 + sub*VV + v] = a.x;
        Sout[o1*104 + sub*VV + v] = b.x;
        s10 += a.x; s20 += a.x*a.x;
        s11 += b.x; s21 += b.x*b.x;
        if (p < 12) {
            Sout[o0*104 + sub*VV + v + 1] = a.y;
            Sout[o1*104 + sub*VV + v + 1] = b.y;
            s10 += a.y; s20 += a.y*a.y;
            s11 += b.y; s21 += b.y*b.y;
        }
    }
    atomicAdd(&smStat[o0],      s10);
    atomicAdd(&smStat[64 + o0], s20);
    atomicAdd(&smStat[o1],      s11);
    atomicAdd(&smStat[64 + o1], s21);
    __syncthreads();
    atomicAdd(&g_stats[tid], smStat[tid]);

    // --- coalesced float4 store of the conv output ---
    float4* cv4 = reinterpret_cast<float4*>(g_conv);
    for (int idx = tid; idx < CC*VV; idx += 128) {
        int o = idx / VV;
        int q = idx - o*VV;
        float4 val = *reinterpret_cast<const float4*>(Sout + o*104 + q*4);
        unsigned gb = ((unsigned)(n*CC + o)*TT + t0)*VV;
        cv4[(gb >> 2) + q] = val;
    }
}

// ---------------------------------------------------------------------------
// stats: fold mean/var into per-channel scale/shift
// ---------------------------------------------------------------------------
__global__ void stats_k(const float* __restrict__ gamma, const float* __restrict__ beta) {
    int o = threadIdx.x;
    if (o < CC) {
        const float inv = 1.f / (float)CNT_F;
        float mean = g_stats[o] * inv;
        float var  = g_stats[64 + o] * inv - mean*mean;
        float sc = gamma[o] * rsqrtf(var + 1e-5f);
        g_scale[o] = sc;
        g_shift[o] = beta[o] - mean*sc;
    }
}

// ---------------------------------------------------------------------------
// pass 2: out = relu(scale[c]*conv + shift[c] + x), streaming float4
// ---------------------------------------------------------------------------
__global__ void bn_apply(const float4* __restrict__ xv, float4* __restrict__ ov) {
    const float4* cv = reinterpret_cast<const float4*>(g_conv);
    const int n4 = TOTAL / 4;
    int stride = gridDim.x * blockDim.x;
    for (int i = blockIdx.x * blockDim.x + threadIdx.x; i < n4; i += stride) {
        int c = (i / 3200) & 63;        // 3200 float4 per (n,c) chunk
        float s  = __ldg(&g_scale[c]);
        float sh = __ldg(&g_shift[c]);
        float4 a = cv[i];
        float4 b = xv[i];
        float4 r;
        r.x = fmaxf(fmaf(s, a.x, sh) + b.x, 0.f);
        r.y = fmaxf(fmaf(s, a.y, sh) + b.y, 0.f);
        r.z = fmaxf(fmaf(s, a.z, sh) + b.z, 0.f);
        r.w = fmaxf(fmaf(s, a.w, sh) + b.w, 0.f);
        ov[i] = r;
    }
}

// ---------------------------------------------------------------------------
extern "C" void kernel_launch(void* const* d_in, const int* in_sizes, int n_in,
                              void* d_out, int out_size) {
    const float* x     = (const float*)d_in[0];
    const float* A     = (const float*)d_in[1];
    const float* W     = (const float*)d_in[2];
    // d_in[3] = b : cancels exactly under training-mode BatchNorm -> unused
    const float* gamma = (const float*)d_in[4];
    const float* beta  = (const float*)d_in[5];
    float* out = (float*)d_out;

    prep_k<<<48, 256>>>(W);
    conv_pass<<<NT/TS, 128>>>(x, A);
    stats_k<<<1, 64>>>(gamma, beta);
    bn_apply<<<4096, 256>>>(reinterpret_cast<const float4*>(x),
                            reinterpret_cast<float4*>(out));
}